// round 16
// baseline (speedup 1.0000x reference)
#include <cuda_runtime.h>
#include <cuda_fp16.h>
#include <cstdint>

// SimpleDistanceLoss:
//   search: S[m][n] = bsq[n] - 2<a_m,b_n> via fp16 m16n8k16 mma.sync, fp16
//           accumulators. bsq folded into the C operand of the first k-step.
//           BN=256 stages; 8 warps in 2(m) x 4(n), warp tile 64x64; A
//           fragments preloaded into registers (tile-invariant).
//           Prep converts B only; each dist CTA converts its own 128 A rows
//           in the prologue, overlapped with the B-tile-0 cp.async.
//   tail:   exact fp32 recompute over the 8 candidate columns of each row's
//           winning group. Separate final-reduce kernel (fusing it into dist
//           measurably slowed the mainloop; keep separate).

#define NPTS   16384
#define DDIM   64
#define NT256  64               // number of 256-col tiles
#define NBLK   128

__device__ uint4 g_bunits[NBLK * 1024];    // fragment-unit layout of B (fp16)
__device__ __align__(16) __half g_bsqh[NPTS];
__device__ float g_bsum[NBLK];

// ---- smem byte offsets ----
#define SM_A     0
#define SM_B0    16384                     // 32768 B (256 cols)
#define SM_B1    49152                     // also A staging during prologue
#define SM_BSQ0  81920                     // 512 B (256 halfs)
#define SM_BSQ1  82432
#define SM_REDV  82944                     // float[128][4]
#define SM_REDM  84992                     // int[128][4]
#define SM_WS    87040                     // float[8]
#define SMEM_BYTES 87072

static __device__ __forceinline__ uint32_t smem_u32(const void* p) {
    uint32_t a;
    asm("{ .reg .u64 t; cvta.to.shared.u64 t, %1; cvt.u32.u64 %0, t; }" : "=r"(a) : "l"(p));
    return a;
}
#define CP16(sm, gp) \
    asm volatile("cp.async.cg.shared.global [%0], [%1], 16;" :: "r"(sm), "l"(gp))
#define CP_COMMIT() asm volatile("cp.async.commit_group;" ::: "memory")
#define CP_WAIT0()  asm volatile("cp.async.wait_group 0;" ::: "memory")

static __device__ __forceinline__ void mma_h_acc(uint32_t c[2], uint32_t a0, uint32_t a1,
                                                 uint32_t a2, uint32_t a3,
                                                 uint32_t b0, uint32_t b1) {
    asm("mma.sync.aligned.m16n8k16.row.col.f16.f16.f16.f16 "
        "{%0,%1},{%2,%3,%4,%5},{%6,%7},{%0,%1};"
        : "+r"(c[0]), "+r"(c[1])
        : "r"(a0), "r"(a1), "r"(a2), "r"(a3), "r"(b0), "r"(b1));
}
static __device__ __forceinline__ void mma_h_init(uint32_t c[2], uint32_t a0, uint32_t a1,
                                                  uint32_t a2, uint32_t a3,
                                                  uint32_t b0, uint32_t b1, uint32_t bq) {
    asm("mma.sync.aligned.m16n8k16.row.col.f16.f16.f16.f16 "
        "{%0,%1},{%2,%3,%4,%5},{%6,%7},{%8,%8};"
        : "=r"(c[0]), "=r"(c[1])
        : "r"(a0), "r"(a1), "r"(a2), "r"(a3), "r"(b0), "r"(b1), "r"(bq));
}

// ---------------------------------------------------------------------------
// Prep (grid 512): B quarter-tiles only. Each block converts 32 rows
// (fp32 -> fp16), computes norms, repacks into the m16n8k16 fragment-unit
// layout:
// Unit (ks, blk, s): 8 halfs {X[x][k],X[x][k+1], X[x+8][k],X[x+8][k+1],
//   X[x][k+8],X[x][k+9], X[x+8][k+8],X[x+8][k+9]}, x = blk*16+(s>>2),
//   k = ks*16+(s&3)*2.
// ---------------------------------------------------------------------------
__global__ __launch_bounds__(256)
void prep_kernel(const float* __restrict__ B) {
    __shared__ __half sh[32 * 64];
    const int tid = threadIdx.x;
    const int b = blockIdx.x;
    const int tile = b >> 2, q2 = b & 3;        // quarter: rows q2*32..+31

    const int r = tid >> 3;                     // local row 0..31
    const int qq = tid & 7;                     // 8 threads per row, 8 floats each
    const float4* s4 = reinterpret_cast<const float4*>(B) +
                       ((size_t)tile * 128 + q2 * 32 + r) * 16 + qq * 2;
    float nrm = 0.f;
    half2* sh2 = reinterpret_cast<half2*>(sh);
#pragma unroll
    for (int i = 0; i < 2; i++) {
        float4 v = s4[i];
        nrm += v.x * v.x + v.y * v.y + v.z * v.z + v.w * v.w;
        sh2[r * 32 + qq * 4 + i * 2 + 0] = __floats2half2_rn(v.x, v.y);
        sh2[r * 32 + qq * 4 + i * 2 + 1] = __floats2half2_rn(v.z, v.w);
    }
    nrm += __shfl_xor_sync(0xffffffffu, nrm, 1);
    nrm += __shfl_xor_sync(0xffffffffu, nrm, 2);
    nrm += __shfl_xor_sync(0xffffffffu, nrm, 4);
    __syncthreads();
    if (qq == 0) g_bsqh[tile * 128 + q2 * 32 + r] = __float2half_rn(nrm);

    uint4* dst = g_bunits + (size_t)tile * 1024;
    {
        int lu = tid;                           // 256 local units, 1 per thread
        int ks = lu >> 6, blkl = (lu >> 5) & 1, s = lu & 31;
        int blk = q2 * 2 + blkl;
        int xl = blkl * 16 + (s >> 2), k = ks * 16 + (s & 3) * 2;
        const uint32_t* p0 = reinterpret_cast<const uint32_t*>(&sh[xl * 64 + k]);
        const uint32_t* p1 = reinterpret_cast<const uint32_t*>(&sh[(xl + 8) * 64 + k]);
        uint4 v;
        v.x = p0[0]; v.y = p1[0]; v.z = p0[4]; v.w = p1[4];
        dst[(ks * 8 + blk) * 32 + s] = v;
    }
}

// ---------------------------------------------------------------------------
// Main: 128 CTAs x 256 threads; 8 warps in 2(m) x 4(n); warp tile 64x64.
// A fragments live in registers for the entire kernel; the prologue converts
// this CTA's 128 A rows (fp32 -> fp16(-2a)) while B tile 0 streams in.
// ---------------------------------------------------------------------------
__global__ __launch_bounds__(256, 1)
void dist_kernel(const float* __restrict__ A, const float* __restrict__ B) {
    extern __shared__ char sm[];
    const uint32_t smb = smem_u32(sm);
    const int tid = threadIdx.x;
    const int wid = tid >> 5, lane = tid & 31;
    const int wm = wid & 1, wn = wid >> 1;     // rows wm*64, cols wn*64 (of 256)
    const int rowbase = blockIdx.x * 128;
    const int c128 = wn >> 1;                  // which 128-col unit group
    const int w4 = (wn & 1) * 4;               // block offset inside the group

    // ---- prologue ----
    {
        // 1) start B tile 0 (256 cols) + bsq cp.async
        const uint4* gB = g_bunits;
#pragma unroll
        for (int i = 0; i < 4; i++) {
            int u = tid + i * 256;
            CP16(smb + SM_B0 + u * 16, gB + u);
            CP16(smb + SM_B0 + 16384 + u * 16, gB + 1024 + u);
        }
        if (tid < 32) CP16(smb + SM_BSQ0 + tid * 16, reinterpret_cast<const uint4*>(g_bsqh) + tid);
        CP_COMMIT();

        // 2) convert this CTA's A rows to fp16(-2a) into staging (SM_B1)
        half2* stg2 = reinterpret_cast<half2*>(sm + SM_B1);
        {
            const int row = tid >> 1, hf = tid & 1;
            const float4* ar = reinterpret_cast<const float4*>(A) +
                               ((size_t)(rowbase + row)) * 16 + hf * 8;
#pragma unroll
            for (int i = 0; i < 8; i++) {
                float4 v = ar[i];
                stg2[row * 32 + hf * 16 + i * 2 + 0] = __floats2half2_rn(-2.f * v.x, -2.f * v.y);
                stg2[row * 32 + hf * 16 + i * 2 + 1] = __floats2half2_rn(-2.f * v.z, -2.f * v.w);
            }
        }
        __syncthreads();

        // 3) repack staging -> SM_A fragment units (same unit math as prep)
        const __half* stg = reinterpret_cast<const __half*>(sm + SM_B1);
        uint4* Adst = reinterpret_cast<uint4*>(sm + SM_A);
#pragma unroll
        for (int i = 0; i < 4; i++) {
            int u = tid + i * 256;
            int ks = u >> 8, blk = (u >> 5) & 7, s = u & 31;
            int x = blk * 16 + (s >> 2), k = ks * 16 + (s & 3) * 2;
            const uint32_t* p0 = reinterpret_cast<const uint32_t*>(&stg[x * 64 + k]);
            const uint32_t* p1 = reinterpret_cast<const uint32_t*>(&stg[(x + 8) * 64 + k]);
            uint4 v;
            v.x = p0[0]; v.y = p1[0]; v.z = p0[4]; v.w = p1[4];
            Adst[u] = v;
        }
        CP_WAIT0();
        __syncthreads();   // SM_A visible; staging reads done before t=0 overwrites SM_B1
    }

    // ---- preload A fragments into registers (tile-invariant) ----
    uint4 areg[4][4];
    {
        const uint4* Au = reinterpret_cast<const uint4*>(sm + SM_A);
#pragma unroll
        for (int ks = 0; ks < 4; ks++)
#pragma unroll
            for (int mt = 0; mt < 4; mt++)
                areg[ks][mt] = Au[(ks * 8 + wm * 4 + mt) * 32 + lane];
    }

    float pmin[16];
    int ptile[16];
#pragma unroll
    for (int s = 0; s < 16; s++) { pmin[s] = 3.4e38f; ptile[s] = 0; }

    for (int t = 0; t < NT256; t++) {
        if (t + 1 < NT256) {
            const uint4* gB = g_bunits + (size_t)(t + 1) * 2048;
            const uint32_t dstB = smb + ((t & 1) ? SM_B0 : SM_B1);
#pragma unroll
            for (int i = 0; i < 8; i++) {
                int u = tid + i * 256;
                CP16(dstB + u * 16, gB + u);
            }
            if (tid < 32)
                CP16(smb + ((t & 1) ? SM_BSQ0 : SM_BSQ1) + tid * 16,
                     reinterpret_cast<const uint4*>(g_bsqh + (t + 1) * 256) + tid);
            CP_COMMIT();
        }

        const uint4* Bu = reinterpret_cast<const uint4*>(sm + ((t & 1) ? SM_B1 : SM_B0)) +
                          c128 * 1024;
        const char* bsqs = sm + ((t & 1) ? SM_BSQ1 : SM_BSQ0);

        uint32_t bq[8];
#pragma unroll
        for (int j = 0; j < 8; j++)
            bq[j] = *reinterpret_cast<const uint32_t*>(
                bsqs + (wn * 64 + (j >> 1) * 16 + (j & 1) * 8 + (lane & 3) * 2) * 2);

        uint32_t acc[4][8][2];
#pragma unroll
        for (int ks = 0; ks < 4; ks++) {
            uint4 bf[4];
#pragma unroll
            for (int p = 0; p < 4; p++)
                bf[p] = Bu[(ks * 8 + w4 + p) * 32 + lane];
#pragma unroll
            for (int mt = 0; mt < 4; mt++)
#pragma unroll
                for (int p = 0; p < 4; p++) {
                    const uint4 af = areg[ks][mt];
                    if (ks == 0) {
                        mma_h_init(acc[mt][2 * p],     af.x, af.y, af.z, af.w,
                                   bf[p].x, bf[p].z, bq[2 * p]);
                        mma_h_init(acc[mt][2 * p + 1], af.x, af.y, af.z, af.w,
                                   bf[p].y, bf[p].w, bq[2 * p + 1]);
                    } else {
                        mma_h_acc(acc[mt][2 * p],     af.x, af.y, af.z, af.w,
                                  bf[p].x, bf[p].z);
                        mma_h_acc(acc[mt][2 * p + 1], af.x, af.y, af.z, af.w,
                                  bf[p].y, bf[p].w);
                    }
                }
        }

        // fold tile minimum per (mt, row-half) slot across the 8 j-blocks
#pragma unroll
        for (int mt = 0; mt < 4; mt++)
#pragma unroll
            for (int rh = 0; rh < 2; rh++) {
                __half2 mn = *reinterpret_cast<__half2*>(&acc[mt][0][rh]);
#pragma unroll
                for (int j = 1; j < 8; j++)
                    mn = __hmin2(mn, *reinterpret_cast<__half2*>(&acc[mt][j][rh]));
                float2 f = __half22float2(mn);
                const int s = mt * 2 + rh;
                if (f.x < pmin[2 * s + 0]) { pmin[2 * s + 0] = f.x; ptile[2 * s + 0] = t; }
                if (f.y < pmin[2 * s + 1]) { pmin[2 * s + 1] = f.y; ptile[2 * s + 1] = t; }
            }

        CP_WAIT0();
        __syncthreads();
    }

    // ---- per-row winner (group) across parity and the 4 lane-pairs ----
    float* redv = reinterpret_cast<float*>(sm + SM_REDV);
    int*   redm = reinterpret_cast<int*>(sm + SM_REDM);
#pragma unroll
    for (int s = 0; s < 8; s++) {
        float v0 = pmin[2 * s], v1 = pmin[2 * s + 1];
        int h = (v1 < v0) ? 1 : 0;
        float v = h ? v1 : v0;
        int meta = (ptile[2 * s + h] << 5) | (wn << 3) | ((lane & 3) * 2 + h);
#pragma unroll
        for (int mk = 1; mk <= 2; mk <<= 1) {
            float ov = __shfl_xor_sync(0xffffffffu, v, mk);
            int om = __shfl_xor_sync(0xffffffffu, meta, mk);
            if (ov < v) { v = ov; meta = om; }
        }
        if ((lane & 3) == 0) {
            int row = wm * 64 + (s >> 1) * 16 + (s & 1) * 8 + (lane >> 2);
            redv[row * 4 + wn] = v;
            redm[row * 4 + wn] = meta;
        }
    }
    __syncthreads();

    // ---- exact fp32 recompute over the 8 candidate columns of the winner ----
    float* ws = reinterpret_cast<float*>(sm + SM_WS);
    if (tid < 128) {
        float bv = redv[tid * 4 + 0];
        int bm = redm[tid * 4 + 0];
#pragma unroll
        for (int w = 1; w < 4; w++) {
            float v = redv[tid * 4 + w];
            if (v < bv) { bv = v; bm = redm[tid * 4 + w]; }
        }
        int base = (bm >> 5) * 256 + ((bm >> 3) & 3) * 64 + (bm & 7);

        const float4* ar = reinterpret_cast<const float4*>(A) + (size_t)(rowbase + tid) * 16;
        float4 a4[16];
#pragma unroll
        for (int i = 0; i < 16; i++) a4[i] = ar[i];

        float best = 3.4e38f;
#pragma unroll
        for (int jj = 0; jj < 8; jj++) {
            int col = base + (jj >> 1) * 16 + (jj & 1) * 8;
            const float4* br = reinterpret_cast<const float4*>(B) + (size_t)col * 16;
            float s = 0.f;
#pragma unroll
            for (int i = 0; i < 16; i++) {
                float4 b4 = br[i];
                float dx = a4[i].x - b4.x, dy = a4[i].y - b4.y;
                float dz = a4[i].z - b4.z, dw = a4[i].w - b4.w;
                s += dx * dx + dy * dy + dz * dz + dw * dw;
            }
            best = fminf(best, s);
        }
#pragma unroll
        for (int mk = 16; mk; mk >>= 1) best += __shfl_xor_sync(0xffffffffu, best, mk);
        if (lane == 0) ws[wid] = best;
    }
    __syncthreads();
    if (tid == 0) {
        float t = 0.f;
#pragma unroll
        for (int i = 0; i < 4; i++) t += ws[i];
        g_bsum[blockIdx.x] = t;
    }
}

// ---------------------------------------------------------------------------
__global__ void final_reduce_kernel(float* __restrict__ out) {
    int lane = threadIdx.x;
    float v = 0.f;
#pragma unroll
    for (int i = 0; i < NBLK / 32; i++) v += g_bsum[lane + i * 32];
#pragma unroll
    for (int mk = 16; mk; mk >>= 1) v += __shfl_xor_sync(0xffffffffu, v, mk);
    if (lane == 0) out[0] = v;
}

extern "C" void kernel_launch(void* const* d_in, const int* in_sizes, int n_in,
                              void* d_out, int out_size) {
    const float* A = (const float*)d_in[0];
    const float* B = (const float*)d_in[1];
    float* out = (float*)d_out;

    cudaFuncSetAttribute(dist_kernel, cudaFuncAttributeMaxDynamicSharedMemorySize, SMEM_BYTES);

    prep_kernel<<<512, 256>>>(B);
    dist_kernel<<<NBLK, 256, SMEM_BYTES>>>(A, B);
    final_reduce_kernel<<<1, 32>>>(out);
}

// round 17
// speedup vs baseline: 1.0867x; 1.0867x over previous
#include <cuda_runtime.h>
#include <cuda_fp16.h>
#include <cstdint>

// SimpleDistanceLoss:
//   search: S[m][n] = bsq[n] - 2<a_m,b_n> via fp16 m16n8k16 mma.sync, fp16
//           accumulators. bsq folded into the C operand of the first k-step.
//           512-col smem stages processed as two serial 256-col chunks
//           (halves per-tile sync/prefetch overhead); 8 warps in 2(m) x 4(n),
//           warp tile 64x64; A fragments preloaded into registers.
//   tail:   exact fp32 recompute over the 8 candidate columns of each row's
//           winning group. Separate final-reduce kernel.

#define NPTS   16384
#define DDIM   64
#define NT512  32               // number of 512-col tiles
#define NBLK   128

__device__ uint4 g_aunits[NBLK * 1024];    // fragment-unit layout of -2*A (fp16)
__device__ uint4 g_bunits[NBLK * 1024];    // fragment-unit layout of B (fp16)
__device__ __align__(16) __half g_bsqh[NPTS];
__device__ float g_bsum[NBLK];

// ---- smem byte offsets ----
#define SM_A     0
#define SM_B0    16384                     // 65536 B (512 cols)
#define SM_B1    81920
#define SM_BSQ0  147456                    // 1024 B (512 halfs)
#define SM_BSQ1  148480
#define SM_REDV  149504                    // float[128][4]
#define SM_REDM  151552                    // int[128][4]
#define SM_WS    153600                    // float[8]
#define SMEM_BYTES 153632

static __device__ __forceinline__ uint32_t smem_u32(const void* p) {
    uint32_t a;
    asm("{ .reg .u64 t; cvta.to.shared.u64 t, %1; cvt.u32.u64 %0, t; }" : "=r"(a) : "l"(p));
    return a;
}
#define CP16(sm, gp) \
    asm volatile("cp.async.cg.shared.global [%0], [%1], 16;" :: "r"(sm), "l"(gp))
#define CP_COMMIT() asm volatile("cp.async.commit_group;" ::: "memory")
#define CP_WAIT0()  asm volatile("cp.async.wait_group 0;" ::: "memory")

static __device__ __forceinline__ void mma_h_acc(uint32_t c[2], uint32_t a0, uint32_t a1,
                                                 uint32_t a2, uint32_t a3,
                                                 uint32_t b0, uint32_t b1) {
    asm("mma.sync.aligned.m16n8k16.row.col.f16.f16.f16.f16 "
        "{%0,%1},{%2,%3,%4,%5},{%6,%7},{%0,%1};"
        : "+r"(c[0]), "+r"(c[1])
        : "r"(a0), "r"(a1), "r"(a2), "r"(a3), "r"(b0), "r"(b1));
}
static __device__ __forceinline__ void mma_h_init(uint32_t c[2], uint32_t a0, uint32_t a1,
                                                  uint32_t a2, uint32_t a3,
                                                  uint32_t b0, uint32_t b1, uint32_t bq) {
    asm("mma.sync.aligned.m16n8k16.row.col.f16.f16.f16.f16 "
        "{%0,%1},{%2,%3,%4,%5},{%6,%7},{%8,%8};"
        : "=r"(c[0]), "=r"(c[1])
        : "r"(a0), "r"(a1), "r"(a2), "r"(a3), "r"(b0), "r"(b1), "r"(bq));
}

// ---------------------------------------------------------------------------
// Prep (grid 1024): blocks 0..511 -> A quarter-tiles, 512..1023 -> B.
// Each block converts 32 rows (fp32 -> fp16, A scaled by -2), computes norms,
// repacks into the m16n8k16 fragment-unit layout:
// Unit (ks, blk, s): 8 halfs {X[x][k],X[x][k+1], X[x+8][k],X[x+8][k+1],
//   X[x][k+8],X[x][k+9], X[x+8][k+8],X[x+8][k+9]}, x = blk*16+(s>>2),
//   k = ks*16+(s&3)*2.
// ---------------------------------------------------------------------------
__global__ __launch_bounds__(256)
void prep_kernel(const float* __restrict__ A, const float* __restrict__ B) {
    __shared__ __half sh[32 * 64];
    const int tid = threadIdx.x;
    const int b = blockIdx.x;

    const bool isB = b >= 512;
    const int t4 = b & 511;
    const int tile = t4 >> 2, q2 = t4 & 3;      // quarter: rows q2*32..+31
    const float sc = isB ? 1.0f : -2.0f;

    const int r = tid >> 3;                     // local row 0..31
    const int qq = tid & 7;                     // 8 threads per row, 8 floats each
    const float4* s4 = reinterpret_cast<const float4*>(isB ? B : A) +
                       ((size_t)tile * 128 + q2 * 32 + r) * 16 + qq * 2;
    float nrm = 0.f;
    half2* sh2 = reinterpret_cast<half2*>(sh);
#pragma unroll
    for (int i = 0; i < 2; i++) {
        float4 v = s4[i];
        nrm += v.x * v.x + v.y * v.y + v.z * v.z + v.w * v.w;
        sh2[r * 32 + qq * 4 + i * 2 + 0] = __floats2half2_rn(sc * v.x, sc * v.y);
        sh2[r * 32 + qq * 4 + i * 2 + 1] = __floats2half2_rn(sc * v.z, sc * v.w);
    }
    nrm += __shfl_xor_sync(0xffffffffu, nrm, 1);
    nrm += __shfl_xor_sync(0xffffffffu, nrm, 2);
    nrm += __shfl_xor_sync(0xffffffffu, nrm, 4);
    __syncthreads();
    if (isB && qq == 0) g_bsqh[tile * 128 + q2 * 32 + r] = __float2half_rn(nrm);

    uint4* dst = (isB ? g_bunits : g_aunits) + (size_t)tile * 1024;
    {
        int lu = tid;                           // 256 local units, 1 per thread
        int ks = lu >> 6, blkl = (lu >> 5) & 1, s = lu & 31;
        int blk = q2 * 2 + blkl;
        int xl = blkl * 16 + (s >> 2), k = ks * 16 + (s & 3) * 2;
        const uint32_t* p0 = reinterpret_cast<const uint32_t*>(&sh[xl * 64 + k]);
        const uint32_t* p1 = reinterpret_cast<const uint32_t*>(&sh[(xl + 8) * 64 + k]);
        uint4 v;
        v.x = p0[0]; v.y = p1[0]; v.z = p0[4]; v.w = p1[4];
        dst[(ks * 8 + blk) * 32 + s] = v;
    }
}

// ---------------------------------------------------------------------------
// Main: 128 CTAs x 256 threads; 8 warps in 2(m) x 4(n); warp tile 64x64.
// A fragments live in registers; 512-col stages, two serial 256-col chunks.
// ---------------------------------------------------------------------------
__global__ __launch_bounds__(256, 1)
void dist_kernel(const float* __restrict__ A, const float* __restrict__ B) {
    extern __shared__ char sm[];
    const uint32_t smb = smem_u32(sm);
    const int tid = threadIdx.x;
    const int wid = tid >> 5, lane = tid & 31;
    const int wm = wid & 1, wn = wid >> 1;     // rows wm*64, cols wn*64 (of 256)
    const int rowbase = blockIdx.x * 128;
    const int c128 = wn >> 1;                  // which 128-col unit group
    const int w4 = (wn & 1) * 4;               // block offset inside the group

    // ---- prologue: A units + B tile 0 (512 cols) + bsq ----
    {
        const uint4* gA = g_aunits + (size_t)blockIdx.x * 1024;
        const uint4* gB = g_bunits;
#pragma unroll
        for (int i = 0; i < 4; i++) {
            int u = tid + i * 256;
            CP16(smb + SM_A + u * 16, gA + u);
        }
#pragma unroll
        for (int i = 0; i < 16; i++) {
            int u = tid + i * 256;
            CP16(smb + SM_B0 + u * 16, gB + u);
        }
        if (tid < 64) CP16(smb + SM_BSQ0 + tid * 16, reinterpret_cast<const uint4*>(g_bsqh) + tid);
        CP_COMMIT();
        CP_WAIT0();
        __syncthreads();
    }

    // ---- preload A fragments into registers (tile-invariant) ----
    uint4 areg[4][4];
    {
        const uint4* Au = reinterpret_cast<const uint4*>(sm + SM_A);
#pragma unroll
        for (int ks = 0; ks < 4; ks++)
#pragma unroll
            for (int mt = 0; mt < 4; mt++)
                areg[ks][mt] = Au[(ks * 8 + wm * 4 + mt) * 32 + lane];
    }

    float pmin[16];
    int ptile[16];
#pragma unroll
    for (int s = 0; s < 16; s++) { pmin[s] = 3.4e38f; ptile[s] = 0; }

    for (int t = 0; t < NT512; t++) {
        if (t + 1 < NT512) {
            const uint4* gB = g_bunits + (size_t)(t + 1) * 4096;
            const uint32_t dstB = smb + ((t & 1) ? SM_B0 : SM_B1);
#pragma unroll
            for (int i = 0; i < 16; i++) {
                int u = tid + i * 256;
                CP16(dstB + u * 16, gB + u);
            }
            if (tid < 64)
                CP16(smb + ((t & 1) ? SM_BSQ0 : SM_BSQ1) + tid * 16,
                     reinterpret_cast<const uint4*>(g_bsqh + (t + 1) * 512) + tid);
            CP_COMMIT();
        }

        const uint4* stage = reinterpret_cast<const uint4*>(sm + ((t & 1) ? SM_B1 : SM_B0));
        const char* bsq_stage = sm + ((t & 1) ? SM_BSQ1 : SM_BSQ0);

#pragma unroll
        for (int nc = 0; nc < 2; nc++) {
            const int tc = t * 2 + nc;          // 256-col chunk index, 0..63
            const uint4* Bu = stage + (nc * 2 + c128) * 1024;
            const char* bsqs = bsq_stage + nc * 512;

            uint32_t bq[8];
#pragma unroll
            for (int j = 0; j < 8; j++)
                bq[j] = *reinterpret_cast<const uint32_t*>(
                    bsqs + (wn * 64 + (j >> 1) * 16 + (j & 1) * 8 + (lane & 3) * 2) * 2);

            uint32_t acc[4][8][2];
#pragma unroll
            for (int ks = 0; ks < 4; ks++) {
                uint4 bf[4];
#pragma unroll
                for (int p = 0; p < 4; p++)
                    bf[p] = Bu[(ks * 8 + w4 + p) * 32 + lane];
#pragma unroll
                for (int mt = 0; mt < 4; mt++)
#pragma unroll
                    for (int p = 0; p < 4; p++) {
                        const uint4 af = areg[ks][mt];
                        if (ks == 0) {
                            mma_h_init(acc[mt][2 * p],     af.x, af.y, af.z, af.w,
                                       bf[p].x, bf[p].z, bq[2 * p]);
                            mma_h_init(acc[mt][2 * p + 1], af.x, af.y, af.z, af.w,
                                       bf[p].y, bf[p].w, bq[2 * p + 1]);
                        } else {
                            mma_h_acc(acc[mt][2 * p],     af.x, af.y, af.z, af.w,
                                      bf[p].x, bf[p].z);
                            mma_h_acc(acc[mt][2 * p + 1], af.x, af.y, af.z, af.w,
                                      bf[p].y, bf[p].w);
                        }
                    }
            }

            // fold chunk minimum per (mt, row-half) slot across the 8 j-blocks
#pragma unroll
            for (int mt = 0; mt < 4; mt++)
#pragma unroll
                for (int rh = 0; rh < 2; rh++) {
                    __half2 mn = *reinterpret_cast<__half2*>(&acc[mt][0][rh]);
#pragma unroll
                    for (int j = 1; j < 8; j++)
                        mn = __hmin2(mn, *reinterpret_cast<__half2*>(&acc[mt][j][rh]));
                    float2 f = __half22float2(mn);
                    const int s = mt * 2 + rh;
                    if (f.x < pmin[2 * s + 0]) { pmin[2 * s + 0] = f.x; ptile[2 * s + 0] = tc; }
                    if (f.y < pmin[2 * s + 1]) { pmin[2 * s + 1] = f.y; ptile[2 * s + 1] = tc; }
                }
        }

        CP_WAIT0();
        __syncthreads();
    }

    // ---- per-row winner (group) across parity and the 4 lane-pairs ----
    float* redv = reinterpret_cast<float*>(sm + SM_REDV);
    int*   redm = reinterpret_cast<int*>(sm + SM_REDM);
#pragma unroll
    for (int s = 0; s < 8; s++) {
        float v0 = pmin[2 * s], v1 = pmin[2 * s + 1];
        int h = (v1 < v0) ? 1 : 0;
        float v = h ? v1 : v0;
        int meta = (ptile[2 * s + h] << 5) | (wn << 3) | ((lane & 3) * 2 + h);
#pragma unroll
        for (int mk = 1; mk <= 2; mk <<= 1) {
            float ov = __shfl_xor_sync(0xffffffffu, v, mk);
            int om = __shfl_xor_sync(0xffffffffu, meta, mk);
            if (ov < v) { v = ov; meta = om; }
        }
        if ((lane & 3) == 0) {
            int row = wm * 64 + (s >> 1) * 16 + (s & 1) * 8 + (lane >> 2);
            redv[row * 4 + wn] = v;
            redm[row * 4 + wn] = meta;
        }
    }
    __syncthreads();

    // ---- exact fp32 recompute over the 8 candidate columns of the winner ----
    float* ws = reinterpret_cast<float*>(sm + SM_WS);
    if (tid < 128) {
        float bv = redv[tid * 4 + 0];
        int bm = redm[tid * 4 + 0];
#pragma unroll
        for (int w = 1; w < 4; w++) {
            float v = redv[tid * 4 + w];
            if (v < bv) { bv = v; bm = redm[tid * 4 + w]; }
        }
        int base = (bm >> 5) * 256 + ((bm >> 3) & 3) * 64 + (bm & 7);

        const float4* ar = reinterpret_cast<const float4*>(A) + (size_t)(rowbase + tid) * 16;
        float4 a4[16];
#pragma unroll
        for (int i = 0; i < 16; i++) a4[i] = ar[i];

        float best = 3.4e38f;
#pragma unroll
        for (int jj = 0; jj < 8; jj++) {
            int col = base + (jj >> 1) * 16 + (jj & 1) * 8;
            const float4* br = reinterpret_cast<const float4*>(B) + (size_t)col * 16;
            float s = 0.f;
#pragma unroll
            for (int i = 0; i < 16; i++) {
                float4 b4 = br[i];
                float dx = a4[i].x - b4.x, dy = a4[i].y - b4.y;
                float dz = a4[i].z - b4.z, dw = a4[i].w - b4.w;
                s += dx * dx + dy * dy + dz * dz + dw * dw;
            }
            best = fminf(best, s);
        }
#pragma unroll
        for (int mk = 16; mk; mk >>= 1) best += __shfl_xor_sync(0xffffffffu, best, mk);
        if (lane == 0) ws[wid] = best;
    }
    __syncthreads();
    if (tid == 0) {
        float t = 0.f;
#pragma unroll
        for (int i = 0; i < 4; i++) t += ws[i];
        g_bsum[blockIdx.x] = t;
    }
}

// ---------------------------------------------------------------------------
__global__ void final_reduce_kernel(float* __restrict__ out) {
    int lane = threadIdx.x;
    float v = 0.f;
#pragma unroll
    for (int i = 0; i < NBLK / 32; i++) v += g_bsum[lane + i * 32];
#pragma unroll
    for (int mk = 16; mk; mk >>= 1) v += __shfl_xor_sync(0xffffffffu, v, mk);
    if (lane == 0) out[0] = v;
}

extern "C" void kernel_launch(void* const* d_in, const int* in_sizes, int n_in,
                              void* d_out, int out_size) {
    const float* A = (const float*)d_in[0];
    const float* B = (const float*)d_in[1];
    float* out = (float*)d_out;

    cudaFuncSetAttribute(dist_kernel, cudaFuncAttributeMaxDynamicSharedMemorySize, SMEM_BYTES);

    prep_kernel<<<1024, 256>>>(A, B);
    dist_kernel<<<NBLK, 256, SMEM_BYTES>>>(A, B);
    final_reduce_kernel<<<1, 32>>>(out);
}